// round 14
// baseline (speedup 1.0000x reference)
#include <cuda_runtime.h>
#include <cuda_bf16.h>
#include <cstdint>
#include <cstring>

// ---------------------------------------------------------------------------
// Problem constants
// ---------------------------------------------------------------------------
#define B_TOTAL 262144
#define NIN 66
#define NE  50
#define NA  20
#define MTILE 64             // rows per CTA (halved: 1 m16 slab per warp)
#define THREADS 128          // 4 warps, 16 rows each
#define NITER 33             // 33 x 40 cols = 1320 = 66*20
#define NPI 40               // cols per iteration (2 features)
#define NCHUNKS 5            // five m16n8 chunks per iteration
#define KSTEPS 10            // K = 160 bf16 (152 real + pad)
#define KPAIRS 5             // uint4-packed pairs of ksteps
#define XPITCH 67
#define EWPITCH 52

// smem byte offsets: 3 B buffers + x tile; E_W overlays B0/B1 (phase-1 only)
#define BITER 12800          // bytes per iteration's B fragments
#define OFF_B0 0
#define OFF_B1 12800
#define OFF_B2 25600
#define OFF_X  38400         // x tile: 64*67*4 = 17152
#define SMEM_BYTES 55552     // -> 4 CTAs/SM (4 warps/SMSP, independent CTAs)

// ---------------------------------------------------------------------------
// Pre-packed B fragments (global): [iter][chunk][kpair][lane][4] u32.
// Lane's uint4 = {b0(ks=2kp), b1(2kp), b0(2kp+1), b1(2kp+1)}.
// ---------------------------------------------------------------------------
__device__ __align__(16) uint32_t b_img[NITER * NCHUNKS * KPAIRS * 128];

// ---------------------------------------------------------------------------
// Helpers
// ---------------------------------------------------------------------------
__device__ __forceinline__ uint32_t pack_bf16(float lo, float hi) {
    __nv_bfloat162 v = __floats2bfloat162_rn(lo, hi);
    uint32_t u; memcpy(&u, &v, 4); return u;
}
__device__ __forceinline__ void cp16(void* s, const void* g) {
    uint32_t sa;
    asm("{ .reg .u64 t; cvta.to.shared.u64 t, %1; cvt.u32.u64 %0, t; }"
        : "=r"(sa) : "l"(s));
    asm volatile("cp.async.ca.shared.global [%0], [%1], 16;" :: "r"(sa), "l"(g));
}
#define CP_COMMIT() asm volatile("cp.async.commit_group;")
#define CP_WAIT1()  asm volatile("cp.async.wait_group 1;")

__device__ __forceinline__ void mma16816(float* c, const uint32_t* a,
                                         uint32_t b0, uint32_t b1) {
    asm volatile(
        "mma.sync.aligned.m16n8k16.row.col.f32.bf16.bf16.f32 "
        "{%0,%1,%2,%3}, {%4,%5,%6,%7}, {%8,%9}, {%0,%1,%2,%3};"
        : "+f"(c[0]), "+f"(c[1]), "+f"(c[2]), "+f"(c[3])
        : "r"(a[0]), "r"(a[1]), "r"(a[2]), "r"(a[3]), "r"(b0), "r"(b1));
}

// packed f32x2 fma (phase 1)
__device__ __forceinline__ unsigned long long dup2(float v) {
    unsigned long long r; asm("mov.b64 %0, {%1, %1};" : "=l"(r) : "f"(v)); return r;
}
__device__ __forceinline__ void fma2(unsigned long long& d, unsigned long long a,
                                     unsigned long long b) {
    asm("fma.rn.f32x2 %0, %1, %2, %0;" : "+l"(d) : "l"(a), "l"(b));
}
__device__ __forceinline__ float lo32(unsigned long long v) { return __uint_as_float((unsigned)v); }
__device__ __forceinline__ float hi32(unsigned long long v) { return __uint_as_float((unsigned)(v >> 32)); }

// Augmented-E column-pair select (compile-time j): cols 2j,2j+1 of
// [Eh(0..49) | El(50..99) | Eh(100..149) | 1,1 (150..151) | 0 (152..159)]
__device__ __forceinline__ uint32_t colsel(const uint32_t* Ehp, const uint32_t* Elp,
                                           uint32_t one2, int j) {
    if (j < 25) return Ehp[j];
    if (j < 50) return Elp[j - 25];
    if (j < 75) return Ehp[j - 50];
    if (j == 75) return one2;
    return 0u;
}

// ---------------------------------------------------------------------------
// Prep kernel (verified, unchanged): B fragments for W[k][n], n = i*20 + a:
//   k<50: Wh | k<100: Wh | k<150: Wl residual | 150/151: bias hi/lo | else 0
// ---------------------------------------------------------------------------
__global__ void prep_kernel(const float* __restrict__ AW, const float* __restrict__ Ab) {
    int idx = blockIdx.x * 256 + threadIdx.x;
    if (idx >= NITER * NCHUNKS * KPAIRS * 128) return;
    int r    = idx & 3;
    int lane = (idx >> 2) & 31;
    int rest = idx >> 7;
    int kp = rest % KPAIRS;
    int ch = (rest / KPAIRS) % NCHUNKS;
    int it = rest / (KPAIRS * NCHUNKS);

    int ks  = 2 * kp + (r >> 1);
    int reg = r & 1;
    int n = it * NPI + ch * 8 + (lane >> 2);
    int i = n / NA, a = n % NA;
    int k0 = ks * 16 + (lane & 3) * 2 + reg * 8;

    float v[2];
#pragma unroll
    for (int t = 0; t < 2; ++t) {
        int k = k0 + t;
        float val = 0.0f;
        if (k < 100) {
            val = AW[i * 1000 + (k % 50) * 20 + a];
        } else if (k < 150) {
            float w = AW[i * 1000 + (k - 100) * 20 + a];
            val = w - __bfloat162float(__float2bfloat16(w));
        } else if (k == 150) {
            val = Ab[i * 20 + a];
        } else if (k == 151) {
            float b = Ab[i * 20 + a];
            val = b - __bfloat162float(__float2bfloat16(b));
        }
        v[t] = val;
    }
    b_img[idx] = pack_bf16(v[0], v[1]);
}

// ---------------------------------------------------------------------------
// Main kernel: 64 rows/CTA, 4 warps, 16 rows (one m16 slab) per warp.
// Warp w owns rows base rbase = (w&1)*32 + ((w>>1)&1)*16.
// Phase 1 computes E for row (tid & 63) -> warp lanes hold a consistent
// 32-row block, so A-fragment shuffles stay intra-warp.
// ---------------------------------------------------------------------------
__global__ void __launch_bounds__(THREADS, 4)
attn_mma(const float* __restrict__ x,  const float* __restrict__ EW,
         const float* __restrict__ Eb, float* __restrict__ out)
{
    extern __shared__ __align__(16) unsigned char smem[];
    float* x_sh  = reinterpret_cast<float*>(smem + OFF_X);
    float* ew_sh = reinterpret_cast<float*>(smem);        // overlays B0/B1, phase-1 only

    const int tid = threadIdx.x;
    const int wid = tid >> 5;
    const int lid = tid & 31;
    const int g   = lid >> 2;      // fragment group row
    const int tig = lid & 3;       // thread-in-group
    const int sb  = ((wid >> 1) & 1) * 16;        // shuffle source-lane base
    const int rbase = (wid & 1) * 32 + sb;        // this warp's MMA row base
    const long long base = (long long)blockIdx.x * MTILE;
    const unsigned char* bg = reinterpret_cast<const unsigned char*>(b_img);

    // Stage x tile + E_W (E_W into the B-buffer region).
    const float* xg = x + base * NIN;
    for (int idx = tid; idx < MTILE * NIN; idx += THREADS)
        x_sh[(idx / NIN) * XPITCH + (idx % NIN)] = xg[idx];
    for (int idx = tid; idx < NIN * NE; idx += THREADS)
        ew_sh[(idx / NE) * EWPITCH + (idx % NE)] = EW[idx];
    __syncthreads();

    // ---------------- Phase 1: E = tanh(x @ E_W + E_b), row = tid & 63 ------
    // (threads tid and tid+64 duplicate the same row so every warp's lanes
    //  hold the E of a consistent 32-row block)
    const int row1p = tid & 63;
    const float* xr = x_sh + row1p * XPITCH;
    unsigned long long eacc[NE / 2];
#pragma unroll
    for (int p = 0; p < NE / 2; ++p) eacc[p] = 0ULL;
#pragma unroll 2
    for (int i = 0; i < NIN; ++i) {
        unsigned long long xv = dup2(xr[i]);
        const float* wrow = ew_sh + i * EWPITCH;
        const ulonglong2* w2 = reinterpret_cast<const ulonglong2*>(wrow);
#pragma unroll
        for (int q = 0; q < 12; ++q) {
            ulonglong2 wv = w2[q];
            fma2(eacc[2 * q], xv, wv.x);
            fma2(eacc[2 * q + 1], xv, wv.y);
        }
        unsigned long long wt = reinterpret_cast<const unsigned long long*>(wrow)[24];
        fma2(eacc[24], xv, wt);
    }
    __syncthreads();   // all warps done reading ew_sh; B buffers may overwrite

    // Prefetch B fragments for iters 0 and 1 (into bufs 0,1 = dead EW region).
    for (int j = tid; j < BITER / 16; j += THREADS)
        cp16(smem + OFF_B0 + j * 16, bg + j * 16);
    CP_COMMIT();
    for (int j = tid; j < BITER / 16; j += THREADS)
        cp16(smem + OFF_B1 + j * 16, bg + BITER + j * 16);
    CP_COMMIT();

    // Packed bf16 hi/lo split of E (this thread's phase-1 row).
    uint32_t Ehp[25], Elp[25];
#pragma unroll
    for (int p = 0; p < NE / 2; ++p) {
        float e0 = tanhf(lo32(eacc[p]) + __ldg(Eb + 2 * p));
        float e1 = tanhf(hi32(eacc[p]) + __ldg(Eb + 2 * p + 1));
        __nv_bfloat162 h2 = __floats2bfloat162_rn(e0, e1);
        uint32_t hv; memcpy(&hv, &h2, 4);
        float r0 = e0 - __bfloat162float(__low2bfloat16(h2));
        float r1 = e1 - __bfloat162float(__high2bfloat16(h2));
        Ehp[p] = hv;
        Elp[p] = pack_bf16(r0, r1);
    }
    const uint32_t one2 = pack_bf16(1.0f, 1.0f);

    // Build A fragments via warp shuffle (one m16 slab: rows rbase..rbase+15).
    // Lane l of this warp holds E of row (wid&1)*32 + l; source lanes sb+g, sb+g+8.
    uint32_t Af[KSTEPS][4];
#pragma unroll
    for (int ks = 0; ks < KSTEPS; ++ks) {
#pragma unroll
        for (int t = 0; t < 4; ++t) {
            uint32_t v0 = colsel(Ehp, Elp, one2, 8 * ks + t);
            uint32_t v1 = colsel(Ehp, Elp, one2, 8 * ks + 4 + t);
            uint32_t r0 = __shfl_sync(0xffffffffu, v0, sb + g);
            uint32_t r1 = __shfl_sync(0xffffffffu, v0, sb + g + 8);
            uint32_t r2 = __shfl_sync(0xffffffffu, v1, sb + g);
            uint32_t r3 = __shfl_sync(0xffffffffu, v1, sb + g + 8);
            if (tig == t) {
                Af[ks][0] = r0; Af[ks][1] = r1;
                Af[ks][2] = r2; Af[ks][3] = r3;
            }
        }
    }

    // ---------------- Main loop: 33 iterations of 40 columns ----------------
#pragma unroll 1
    for (int c = 0; c < NITER; ++c) {
        CP_WAIT1();
        __syncthreads();         // all warps entered iter c; buf c%3 resident

        const uint4* bbuf = reinterpret_cast<const uint4*>(
            smem + (c % 3) * BITER);

        float C[NCHUNKS][4];
#pragma unroll
        for (int ch = 0; ch < NCHUNKS; ++ch)
#pragma unroll
            for (int q = 0; q < 4; ++q) C[ch][q] = 0.0f;

#pragma unroll
        for (int ch = 0; ch < NCHUNKS; ++ch) {
#pragma unroll
            for (int kp = 0; kp < KPAIRS; ++kp) {
                uint4 bv = bbuf[(ch * KPAIRS + kp) * 32 + lid];  // LDS.128
                mma16816(C[ch], Af[2 * kp],     bv.x, bv.y);
                mma16816(C[ch], Af[2 * kp + 1], bv.z, bv.w);
            }
        }

        if (c + 2 < NITER) {     // refill buf (c+2)%3 (1-bar/3-buf invariant)
            const unsigned char* src = bg + (size_t)(c + 2) * BITER;
            for (int j = tid; j < BITER / 16; j += THREADS)
                cp16(smem + ((c + 2) % 3) * BITER + j * 16, src + j * 16);
        }
        CP_COMMIT();

        // ---- Softmax in registers + x update (one slab) --------------------
        {
            float ex[NCHUNKS][4];
#pragma unroll
            for (int ch = 0; ch < NCHUNKS; ++ch)
#pragma unroll
                for (int q = 0; q < 4; ++q) ex[ch][q] = __expf(C[ch][q]);

            float p00 = ex[0][0] + ex[0][1] + ex[1][0] + ex[1][1];  // f0, row g
            float p01 = ex[0][2] + ex[0][3] + ex[1][2] + ex[1][3];  // f0, row g+8
            float p10 = ex[3][0] + ex[3][1] + ex[4][0] + ex[4][1];  // f1, row g
            float p11 = ex[3][2] + ex[3][3] + ex[4][2] + ex[4][3];  // f1, row g+8
            if (tig < 2) { p00 += ex[2][0] + ex[2][1]; p01 += ex[2][2] + ex[2][3]; }
            else         { p10 += ex[2][0] + ex[2][1]; p11 += ex[2][2] + ex[2][3]; }

            p00 += __shfl_xor_sync(0xffffffffu, p00, 1);
            p00 += __shfl_xor_sync(0xffffffffu, p00, 2);
            p01 += __shfl_xor_sync(0xffffffffu, p01, 1);
            p01 += __shfl_xor_sync(0xffffffffu, p01, 2);
            p10 += __shfl_xor_sync(0xffffffffu, p10, 1);
            p10 += __shfl_xor_sync(0xffffffffu, p10, 2);
            p11 += __shfl_xor_sync(0xffffffffu, p11, 1);
            p11 += __shfl_xor_sync(0xffffffffu, p11, 2);

            int row0 = rbase + g;
            int row1 = row0 + 8;
            if (tig == 0) {      // class-1 of f0 = col 1 -> ch0 reg1/reg3
                x_sh[row0 * XPITCH + 2 * c] *= ex[0][1] * __fdividef(1.0f, p00);
                x_sh[row1 * XPITCH + 2 * c] *= ex[0][3] * __fdividef(1.0f, p01);
            } else if (tig == 2) { // class-1 of f1 = col 21 -> ch2 reg1/reg3
                x_sh[row0 * XPITCH + 2 * c + 1] *= ex[2][1] * __fdividef(1.0f, p10);
                x_sh[row1 * XPITCH + 2 * c + 1] *= ex[2][3] * __fdividef(1.0f, p11);
            }
        }
    }
    __syncthreads();

    // Coalesced writeback.
    float* og = out + base * NIN;
    for (int idx = tid; idx < MTILE * NIN; idx += THREADS)
        og[idx] = x_sh[(idx / NIN) * XPITCH + (idx % NIN)];
}

// ---------------------------------------------------------------------------
extern "C" void kernel_launch(void* const* d_in, const int* in_sizes, int n_in,
                              void* d_out, int out_size) {
    const float* x  = (const float*)d_in[0];
    const float* EW = (const float*)d_in[1];
    const float* Eb = (const float*)d_in[2];
    const float* AW = (const float*)d_in[3];
    const float* Ab = (const float*)d_in[4];
    float* out = (float*)d_out;

    int prep_elems = NITER * NCHUNKS * KPAIRS * 128;
    prep_kernel<<<(prep_elems + 255) / 256, 256>>>(AW, Ab);

    cudaFuncSetAttribute(attn_mma,
                         cudaFuncAttributeMaxDynamicSharedMemorySize, SMEM_BYTES);
    attn_mma<<<B_TOTAL / MTILE, THREADS, SMEM_BYTES>>>(x, EW, Eb, out);
}

// round 16
// speedup vs baseline: 1.2788x; 1.2788x over previous
#include <cuda_runtime.h>
#include <cuda_bf16.h>
#include <cstdint>
#include <cstring>

// ---------------------------------------------------------------------------
// Problem constants
// ---------------------------------------------------------------------------
#define B_TOTAL 262144
#define NIN 66
#define NE  50
#define NA  20
#define MTILE 128            // rows per CTA
#define THREADS 128          // 4 warps, 32 rows each (2 m16 slabs)
#define NITER 33             // 33 x 40 cols = 1320 = 66*20
#define NPI 40               // cols per iteration (2 features)
#define NCHUNKS 5            // five m16n8 chunks per iteration
#define KSTEPS 10            // K = 160 bf16 (152 real + pad)
#define KPAIRS 5             // uint4-packed pairs of ksteps
#define XPITCH 67
#define EWPITCH 52

// smem: x tile + E_W only (B comes via LDG now — no buffers, no per-iter bar)
#define OFF_X  0             // 128*67*4 = 34304
#define OFF_EW 34304         // 66*52*4 = 13728
#define SMEM_BYTES 48128     // small; occupancy is register-limited (3 CTAs/SM)

// ---------------------------------------------------------------------------
// Pre-packed B fragments (global): [iter][chunk][kpair][lane][4] u32.
// Lane's uint4 = {b0(ks=2kp), b1(2kp), b0(2kp+1), b1(2kp+1)}; consecutive
// lanes hold consecutive uint4s -> LDG.128 fully coalesced, L1-cacheable.
// ---------------------------------------------------------------------------
__device__ __align__(16) uint32_t b_img[NITER * NCHUNKS * KPAIRS * 128];

// ---------------------------------------------------------------------------
// Helpers
// ---------------------------------------------------------------------------
__device__ __forceinline__ uint32_t pack_bf16(float lo, float hi) {
    __nv_bfloat162 v = __floats2bfloat162_rn(lo, hi);
    uint32_t u; memcpy(&u, &v, 4); return u;
}
__device__ __forceinline__ void mma16816(float* c, const uint32_t* a,
                                         uint32_t b0, uint32_t b1) {
    asm volatile(
        "mma.sync.aligned.m16n8k16.row.col.f32.bf16.bf16.f32 "
        "{%0,%1,%2,%3}, {%4,%5,%6,%7}, {%8,%9}, {%0,%1,%2,%3};"
        : "+f"(c[0]), "+f"(c[1]), "+f"(c[2]), "+f"(c[3])
        : "r"(a[0]), "r"(a[1]), "r"(a[2]), "r"(a[3]), "r"(b0), "r"(b1));
}

// packed f32x2 fma (phase 1)
__device__ __forceinline__ unsigned long long dup2(float v) {
    unsigned long long r; asm("mov.b64 %0, {%1, %1};" : "=l"(r) : "f"(v)); return r;
}
__device__ __forceinline__ void fma2(unsigned long long& d, unsigned long long a,
                                     unsigned long long b) {
    asm("fma.rn.f32x2 %0, %1, %2, %0;" : "+l"(d) : "l"(a), "l"(b));
}
__device__ __forceinline__ float lo32(unsigned long long v) { return __uint_as_float((unsigned)v); }
__device__ __forceinline__ float hi32(unsigned long long v) { return __uint_as_float((unsigned)(v >> 32)); }

// Augmented-E column-pair select (compile-time j): cols 2j,2j+1 of
// [Eh(0..49) | El(50..99) | Eh(100..149) | 1,1 (150..151) | 0 (152..159)]
__device__ __forceinline__ uint32_t colsel(const uint32_t* Ehp, const uint32_t* Elp,
                                           uint32_t one2, int j) {
    if (j < 25) return Ehp[j];
    if (j < 50) return Elp[j - 25];
    if (j < 75) return Ehp[j - 50];
    if (j == 75) return one2;
    return 0u;
}

// ---------------------------------------------------------------------------
// Prep kernel (verified, unchanged): B fragments for W[k][n], n = i*20 + a:
//   k<50: Wh | k<100: Wh | k<150: Wl residual | 150/151: bias hi/lo | else 0
// ---------------------------------------------------------------------------
__global__ void prep_kernel(const float* __restrict__ AW, const float* __restrict__ Ab) {
    int idx = blockIdx.x * 256 + threadIdx.x;
    if (idx >= NITER * NCHUNKS * KPAIRS * 128) return;
    int r    = idx & 3;
    int lane = (idx >> 2) & 31;
    int rest = idx >> 7;
    int kp = rest % KPAIRS;
    int ch = (rest / KPAIRS) % NCHUNKS;
    int it = rest / (KPAIRS * NCHUNKS);

    int ks  = 2 * kp + (r >> 1);
    int reg = r & 1;
    int n = it * NPI + ch * 8 + (lane >> 2);
    int i = n / NA, a = n % NA;
    int k0 = ks * 16 + (lane & 3) * 2 + reg * 8;

    float v[2];
#pragma unroll
    for (int t = 0; t < 2; ++t) {
        int k = k0 + t;
        float val = 0.0f;
        if (k < 100) {
            val = AW[i * 1000 + (k % 50) * 20 + a];
        } else if (k < 150) {
            float w = AW[i * 1000 + (k - 100) * 20 + a];
            val = w - __bfloat162float(__float2bfloat16(w));
        } else if (k == 150) {
            val = Ab[i * 20 + a];
        } else if (k == 151) {
            float b = Ab[i * 20 + a];
            val = b - __bfloat162float(__float2bfloat16(b));
        }
        v[t] = val;
    }
    b_img[idx] = pack_bf16(v[0], v[1]);
}

// ---------------------------------------------------------------------------
// Main kernel: NO per-iteration barrier. B fragments via coalesced LDG.128
// (L1-cached; 4 warps/CTA share lines). Warps free-run -> phases stagger ->
// tensor pipe stays fed while sibling warps run their epilogues.
// ---------------------------------------------------------------------------
__global__ void __launch_bounds__(THREADS, 3)
attn_mma(const float* __restrict__ x,  const float* __restrict__ EW,
         const float* __restrict__ Eb, float* __restrict__ out)
{
    extern __shared__ __align__(16) unsigned char smem[];
    float* x_sh  = reinterpret_cast<float*>(smem + OFF_X);
    float* ew_sh = reinterpret_cast<float*>(smem + OFF_EW);

    const int tid = threadIdx.x;
    const int wid = tid >> 5;
    const int lid = tid & 31;
    const int g   = lid >> 2;     // fragment group row
    const int tig = lid & 3;      // thread-in-group
    const long long base = (long long)blockIdx.x * MTILE;

    // Stage x tile + E_W.
    const float* xg = x + base * NIN;
    for (int idx = tid; idx < MTILE * NIN; idx += THREADS)
        x_sh[(idx / NIN) * XPITCH + (idx % NIN)] = xg[idx];
    for (int idx = tid; idx < NIN * NE; idx += THREADS)
        ew_sh[(idx / NE) * EWPITCH + (idx % NE)] = EW[idx];
    __syncthreads();

    // ---------------- Phase 1: E = tanh(x @ E_W + E_b), 1 row/thread --------
    const float* xr = x_sh + tid * XPITCH;
    unsigned long long eacc[NE / 2];
#pragma unroll
    for (int p = 0; p < NE / 2; ++p) eacc[p] = 0ULL;
#pragma unroll 2
    for (int i = 0; i < NIN; ++i) {
        unsigned long long xv = dup2(xr[i]);
        const float* wrow = ew_sh + i * EWPITCH;
        const ulonglong2* w2 = reinterpret_cast<const ulonglong2*>(wrow);
#pragma unroll
        for (int q = 0; q < 12; ++q) {
            ulonglong2 wv = w2[q];
            fma2(eacc[2 * q], xv, wv.x);
            fma2(eacc[2 * q + 1], xv, wv.y);
        }
        unsigned long long wt = reinterpret_cast<const unsigned long long*>(wrow)[24];
        fma2(eacc[24], xv, wt);
    }

    // Packed bf16 hi/lo split of E (this thread's row = tid).
    uint32_t Ehp[25], Elp[25];
#pragma unroll
    for (int p = 0; p < NE / 2; ++p) {
        float e0 = tanhf(lo32(eacc[p]) + __ldg(Eb + 2 * p));
        float e1 = tanhf(hi32(eacc[p]) + __ldg(Eb + 2 * p + 1));
        __nv_bfloat162 h2 = __floats2bfloat162_rn(e0, e1);
        uint32_t hv; memcpy(&hv, &h2, 4);
        float r0 = e0 - __bfloat162float(__low2bfloat16(h2));
        float r1 = e1 - __bfloat162float(__high2bfloat16(h2));
        Ehp[p] = hv;
        Elp[p] = pack_bf16(r0, r1);
    }
    const uint32_t one2 = pack_bf16(1.0f, 1.0f);

    // Build A fragments via warp shuffle (rows of warp wid == its own lanes).
    uint32_t Af[2][KSTEPS][4];
#pragma unroll
    for (int s = 0; s < 2; ++s) {
#pragma unroll
        for (int ks = 0; ks < KSTEPS; ++ks) {
#pragma unroll
            for (int t = 0; t < 4; ++t) {
                uint32_t v0 = colsel(Ehp, Elp, one2, 8 * ks + t);
                uint32_t v1 = colsel(Ehp, Elp, one2, 8 * ks + 4 + t);
                uint32_t r0 = __shfl_sync(0xffffffffu, v0, s * 16 + g);
                uint32_t r1 = __shfl_sync(0xffffffffu, v0, s * 16 + g + 8);
                uint32_t r2 = __shfl_sync(0xffffffffu, v1, s * 16 + g);
                uint32_t r3 = __shfl_sync(0xffffffffu, v1, s * 16 + g + 8);
                if (tig == t) {
                    Af[s][ks][0] = r0; Af[s][ks][1] = r1;
                    Af[s][ks][2] = r2; Af[s][ks][3] = r3;
                }
            }
        }
    }
    // No further CTA-wide sync until writeback: each warp's epilogue touches
    // only its own 32 x_sh rows, and B comes from read-only global memory.

    // ---------------- Main loop: 33 iterations, barrier-free ----------------
    const uint4* bq = reinterpret_cast<const uint4*>(b_img) + lid;
#pragma unroll 1
    for (int c = 0; c < NITER; ++c) {
        const uint4* bi = bq + (size_t)c * (NCHUNKS * KPAIRS * 32);

        float C[2][NCHUNKS][4];
#pragma unroll
        for (int s = 0; s < 2; ++s)
#pragma unroll
            for (int ch = 0; ch < NCHUNKS; ++ch)
#pragma unroll
                for (int q = 0; q < 4; ++q) C[s][ch][q] = 0.0f;

#pragma unroll
        for (int ch = 0; ch < NCHUNKS; ++ch) {
            uint4 bv[KPAIRS];
#pragma unroll
            for (int kp = 0; kp < KPAIRS; ++kp)          // 5 indep LDG.128
                bv[kp] = bi[(ch * KPAIRS + kp) * 32];
#pragma unroll
            for (int kp = 0; kp < KPAIRS; ++kp) {
                mma16816(C[0][ch], Af[0][2 * kp],     bv[kp].x, bv[kp].y);
                mma16816(C[1][ch], Af[1][2 * kp],     bv[kp].x, bv[kp].y);
                mma16816(C[0][ch], Af[0][2 * kp + 1], bv[kp].z, bv[kp].w);
                mma16816(C[1][ch], Af[1][2 * kp + 1], bv[kp].z, bv[kp].w);
            }
        }

        // ---- Softmax in registers + x update (warp-private rows) ----------
#pragma unroll
        for (int s = 0; s < 2; ++s) {
            float ex[NCHUNKS][4];
#pragma unroll
            for (int ch = 0; ch < NCHUNKS; ++ch)
#pragma unroll
                for (int q = 0; q < 4; ++q) ex[ch][q] = __expf(C[s][ch][q]);

            float p00 = ex[0][0] + ex[0][1] + ex[1][0] + ex[1][1];  // f0, row g
            float p01 = ex[0][2] + ex[0][3] + ex[1][2] + ex[1][3];  // f0, row g+8
            float p10 = ex[3][0] + ex[3][1] + ex[4][0] + ex[4][1];  // f1, row g
            float p11 = ex[3][2] + ex[3][3] + ex[4][2] + ex[4][3];  // f1, row g+8
            if (tig < 2) { p00 += ex[2][0] + ex[2][1]; p01 += ex[2][2] + ex[2][3]; }
            else         { p10 += ex[2][0] + ex[2][1]; p11 += ex[2][2] + ex[2][3]; }

            p00 += __shfl_xor_sync(0xffffffffu, p00, 1);
            p00 += __shfl_xor_sync(0xffffffffu, p00, 2);
            p01 += __shfl_xor_sync(0xffffffffu, p01, 1);
            p01 += __shfl_xor_sync(0xffffffffu, p01, 2);
            p10 += __shfl_xor_sync(0xffffffffu, p10, 1);
            p10 += __shfl_xor_sync(0xffffffffu, p10, 2);
            p11 += __shfl_xor_sync(0xffffffffu, p11, 1);
            p11 += __shfl_xor_sync(0xffffffffu, p11, 2);

            int row0 = wid * 32 + s * 16 + g;
            int row1 = row0 + 8;
            if (tig == 0) {      // class-1 of f0 = col 1 -> ch0 reg1/reg3
                x_sh[row0 * XPITCH + 2 * c] *= ex[0][1] * __fdividef(1.0f, p00);
                x_sh[row1 * XPITCH + 2 * c] *= ex[0][3] * __fdividef(1.0f, p01);
            } else if (tig == 2) { // class-1 of f1 = col 21 -> ch2 reg1/reg3
                x_sh[row0 * XPITCH + 2 * c + 1] *= ex[2][1] * __fdividef(1.0f, p10);
                x_sh[row1 * XPITCH + 2 * c + 1] *= ex[2][3] * __fdividef(1.0f, p11);
            }
        }
    }
    __syncthreads();

    // Coalesced writeback.
    float* og = out + base * NIN;
    for (int idx = tid; idx < MTILE * NIN; idx += THREADS)
        og[idx] = x_sh[(idx / NIN) * XPITCH + (idx % NIN)];
}

// ---------------------------------------------------------------------------
extern "C" void kernel_launch(void* const* d_in, const int* in_sizes, int n_in,
                              void* d_out, int out_size) {
    const float* x  = (const float*)d_in[0];
    const float* EW = (const float*)d_in[1];
    const float* Eb = (const float*)d_in[2];
    const float* AW = (const float*)d_in[3];
    const float* Ab = (const float*)d_in[4];
    float* out = (float*)d_out;

    int prep_elems = NITER * NCHUNKS * KPAIRS * 128;
    prep_kernel<<<(prep_elems + 255) / 256, 256>>>(AW, Ab);

    cudaFuncSetAttribute(attn_mma,
                         cudaFuncAttributeMaxDynamicSharedMemorySize, SMEM_BYTES);
    attn_mma<<<B_TOTAL / MTILE, THREADS, SMEM_BYTES>>>(x, EW, Eb, out);
}